// round 14
// baseline (speedup 1.0000x reference)
#include <cuda_runtime.h>
#include <cuda_bf16.h>

// RoIPointPool3d: B=4, N=16384, M=128, C=128, S=512
// Phase 1: 4 boxes per block; 8 warp-stripes; sync-free warp-local ordered
//          compaction per box; one barrier; scan + copy-out.
// Phase 2: block-per-box; stage cnt distinct rows in smem; emit output in
//          4-row groups as aligned float4 stores (one %cnt per group).

#define BB 4
#define NN 16384
#define MM 128
#define CC 128
#define SS 512
#define ROW (3 + CC)         // 131
#define MAXR 192             // 192*131*4 = 100608 B smem -> 2 CTAs/SM
#define NWARP 8
#define STRIPE (NN / NWARP)  // 2048
#define BPB 4                // boxes per select-block
#define GTHREADS 512

__device__ int g_idx[BB * MM * SS];
__device__ int g_cnt[BB * MM];

// ---------------------------------------------------------------- phase 1
__global__ __launch_bounds__(256) void box_select_kernel(
    const float* __restrict__ points,   // (B, N, 3)
    const float* __restrict__ boxes,    // (B, M, 7)
    int B, int N, int M)
{
    extern __shared__ int sIdx[];       // [BPB][NWARP][SS] = 64 KB
    __shared__ int s_wcnt[BPB][NWARP];
    __shared__ int s_woff[BPB][NWARP + 1];

    const int boxBase = blockIdx.x * BPB;
    const int nBoxes  = B * M;
    const int b       = boxBase / M;    // all BPB boxes in same batch (M%BPB==0)

    const int tid  = threadIdx.x;
    const int lane = tid & 31;
    const int wid  = tid >> 5;

    // per-box params (guarded; no-op at these sizes)
    float cx[BPB], cy[BPB], cz[BPB], hx[BPB], hy[BPB], hz[BPB], ca[BPB], sa[BPB];
    #pragma unroll
    for (int q = 0; q < BPB; q++) {
        const int box = (boxBase + q < nBoxes) ? (boxBase + q) : (nBoxes - 1);
        const float* bx = boxes + (size_t)box * 7;
        cx[q] = bx[0]; cy[q] = bx[1];
        const float dzq = bx[5];
        cz[q] = bx[2] + 0.5f * dzq;
        hx[q] = 0.5f * bx[3]; hy[q] = 0.5f * bx[4]; hz[q] = 0.5f * dzq;
        const float rz = bx[6];
        ca[q] = cosf(-rz); sa[q] = sinf(-rz);
    }

    const float* pts = points + (size_t)b * N * 3;

    int wcnt[BPB];
    #pragma unroll
    for (int q = 0; q < BPB; q++) wcnt[q] = 0;

    const int stripe0 = wid * STRIPE;
    for (int it = 0; it < STRIPE / 32; it++) {
        const int i = stripe0 + it * 32 + lane;
        const float x = pts[i * 3 + 0];
        const float y = pts[i * 3 + 1];
        const float z = pts[i * 3 + 2];
        #pragma unroll
        for (int q = 0; q < BPB; q++) {
            const float sx = x - cx[q];
            const float sy = y - cy[q];
            const float lx = sx * ca[q] - sy * sa[q];
            const float ly = sx * sa[q] + sy * ca[q];
            const bool m = (fabsf(z - cz[q]) <= hz[q]) &&
                           (lx > -hx[q]) && (lx < hx[q]) &&
                           (ly > -hy[q]) && (ly < hy[q]);
            const unsigned bal = __ballot_sync(0xffffffffu, m);
            if (m) {
                const int pos = wcnt[q] + __popc(bal & ((1u << lane) - 1u));
                if (pos < SS) sIdx[(q * NWARP + wid) * SS + pos] = i;
            }
            wcnt[q] += __popc(bal);
        }
    }
    if (lane == 0) {
        #pragma unroll
        for (int q = 0; q < BPB; q++)
            s_wcnt[q][wid] = (wcnt[q] < SS) ? wcnt[q] : SS;
    }
    __syncthreads();

    if (tid < BPB) {
        const int q = tid;
        int acc = 0;
        #pragma unroll
        for (int w = 0; w < NWARP; w++) { s_woff[q][w] = acc; acc += s_wcnt[q][w]; }
        s_woff[q][NWARP] = acc;
        if (boxBase + q < nBoxes) g_cnt[boxBase + q] = (acc < SS) ? acc : SS;
    }
    __syncthreads();

    for (int q = 0; q < BPB; q++) {
        if (boxBase + q >= nBoxes) break;
        int* gout = g_idx + (boxBase + q) * SS;
        #pragma unroll 1
        for (int w = 0; w < NWARP; w++) {
            const int off = s_woff[q][w];
            if (off >= SS) break;
            const int n = s_wcnt[q][w];
            const int lim = (off + n > SS) ? (SS - off) : n;
            for (int k = tid; k < lim; k += 256)
                gout[off + k] = sIdx[(q * NWARP + w) * SS + k];
        }
    }
}

// ---------------------------------------------------------------- phase 2
__global__ __launch_bounds__(GTHREADS) void gather_kernel3(
    const float* __restrict__ points,   // (B, N, 3)
    const float* __restrict__ feats,    // (B, N, C)
    float* __restrict__ out,            // (B, M, S, 3+C)
    float* __restrict__ flag_out,       // (B, M) or nullptr
    int B, int N, int M)
{
    extern __shared__ float sm[];       // MAXR * ROW floats

    const int box  = blockIdx.x;
    const int b    = box / M;
    const int tid  = threadIdx.x;
    const int lane = tid & 31;
    const int wid  = tid >> 5;
    const int nw   = GTHREADS / 32;     // 16 warps

    const int cnt = g_cnt[box];
    float* obox = out + (size_t)box * SS * ROW;

    if (flag_out && tid == 0) flag_out[box] = (cnt == 0) ? 1.0f : 0.0f;

    if (cnt == 0) {
        float4* o4 = (float4*)obox;
        const float4 z4 = make_float4(0.f, 0.f, 0.f, 0.f);
        const int V4 = SS * ROW / 4;
        for (int v = tid; v < V4; v += GTHREADS) o4[v] = z4;
        return;
    }

    if (cnt <= MAXR) {
        // --- stage cnt distinct rows in smem (warp per row, float4 feat loads) ---
        for (int r = wid; r < cnt; r += nw) {
            const int idx = g_idx[box * SS + r];
            const float* p   = points + ((size_t)b * N + idx) * 3;
            const float4* f4 = (const float4*)(feats + ((size_t)b * N + idx) * CC);
            float* srow = sm + r * ROW;
            if (lane < 3) srow[lane] = p[lane];
            const float4 v = f4[lane];          // 32 lanes x float4 = 128 floats
            srow[3 + 4 * lane + 0] = v.x;
            srow[3 + 4 * lane + 1] = v.y;
            srow[3 + 4 * lane + 2] = v.z;
            srow[3 + 4 * lane + 3] = v.w;
        }
        __syncthreads();

        // --- emit output in 4-row groups: all stores are aligned float4 ---
        // group g covers rows 4g..4g+3 (524 floats = 131 float4, 16B-aligned)
        const int nGroups = SS / 4;     // 128
        for (int g = wid; g < nGroups; g += nw) {
            const int s0 = 4 * g;
            const int sr0 = s0 % cnt;               // one runtime mod per group
            int sr1 = sr0 + 1; if (sr1 >= cnt) sr1 -= cnt;
            int sr2 = sr1 + 1; if (sr2 >= cnt) sr2 -= cnt;
            int sr3 = sr2 + 1; if (sr3 >= cnt) sr3 -= cnt;
            const float* b0 = sm + sr0 * ROW;
            const float* b1 = sm + sr1 * ROW;
            const float* b2 = sm + sr2 * ROW;
            const float* b3 = sm + sr3 * ROW;

            float4* o4 = (float4*)(obox + (size_t)s0 * ROW);
            #pragma unroll 1
            for (int v = lane; v < ROW; v += 32) {  // 131 float4 per group
                const int e0 = 4 * v;
                float4 val;
                #pragma unroll
                for (int k = 0; k < 4; k++) {
                    const int e = e0 + k;           // 0..523
                    const int rl = e / ROW;         // const-div (umulhi)
                    const int c  = e - rl * ROW;
                    const float* bp = (rl == 0) ? b0 : (rl == 1) ? b1
                                     : (rl == 2) ? b2 : b3;
                    ((float*)&val)[k] = bp[c];
                }
                o4[v] = val;
            }
        }
    } else {
        // --- rare fallback: warp per output row, direct from gmem ---
        for (int s = wid; s < SS; s += nw) {
            const int idx = g_idx[box * SS + (s % cnt)];
            const float* p = points + ((size_t)b * N + idx) * 3;
            const float* f = feats  + ((size_t)b * N + idx) * CC;
            float* o = obox + (size_t)s * ROW;
            #pragma unroll
            for (int c = lane; c < ROW; c += 32)
                o[c] = (c < 3) ? p[c] : f[c - 3];
        }
    }
}

// ---------------------------------------------------------------- launch
extern "C" void kernel_launch(void* const* d_in, const int* in_sizes, int n_in,
                              void* d_out, int out_size)
{
    const float* points = (const float*)d_in[0];  // (B, N, 3)
    const float* feats  = (const float*)d_in[1];  // (B, N, C)
    const float* boxes  = (const float*)d_in[2];  // (B, M, 7)

    const int N = NN, M = MM;
    const int B = in_sizes[2] / (7 * M);
    const int nBoxes = B * M;

    const int selSmem = BPB * NWARP * SS * (int)sizeof(int);    // 65536
    const int gatSmem = MAXR * ROW * (int)sizeof(float);        // 100608
    // Unconditional (no static guards): host-side, idempotent, capture-safe.
    cudaFuncSetAttribute(box_select_kernel,
                         cudaFuncAttributeMaxDynamicSharedMemorySize, selSmem);
    cudaFuncSetAttribute(gather_kernel3,
                         cudaFuncAttributeMaxDynamicSharedMemorySize, gatSmem);

    box_select_kernel<<<(nBoxes + BPB - 1) / BPB, 256, selSmem>>>(points, boxes, B, N, M);

    const long long pooledElems = (long long)nBoxes * SS * ROW;
    float* flag_out = ((long long)out_size >= pooledElems + nBoxes)
                          ? ((float*)d_out + pooledElems) : nullptr;

    gather_kernel3<<<nBoxes, GTHREADS, gatSmem>>>(points, feats, (float*)d_out,
                                                  flag_out, B, N, M);
}